// round 4
// baseline (speedup 1.0000x reference)
#include <cuda_runtime.h>

#define NN   200000
#define EE   1200000
#define ETOT 1400000
#define GG   2048

// ---------------- scratch (device globals: no allocation allowed) ----------
__device__ __align__(16) float g_h0[NN * 64];    // node features (layer in/out)
__device__ __align__(16) float g_hlin[NN * 64];  // h @ W
__device__ __align__(16) float g_hout[NN * 64];  // aggregation accumulator
__device__ float        g_as[NN];
__device__ float        g_ad[NN];
__device__ unsigned int g_mU[NN];                // segment max (ordered uint)
__device__ float        g_den[NN];               // softmax denominator
__device__ float        g_e[ETOT];
__device__ float        g_w[ETOT];
__device__ int          g_src[ETOT];
__device__ int          g_dst[ETOT];
__device__ int          g_batch[NN];
__device__ __align__(16) float g_psum[GG * 64];
__device__ unsigned int g_pmax[GG * 64];
__device__ int          g_cnt[GG];
__device__ float        g_feat[GG * 128];
__device__ float        g_m1[GG * 64];
__device__ float        g_m2[GG * 32];
__device__ int          g_is64;

// ---------------- helpers ---------------------------------------------------
__device__ __forceinline__ unsigned fOrd(float f) {
    unsigned u = __float_as_uint(f);
    return (u & 0x80000000u) ? ~u : (u | 0x80000000u);
}
__device__ __forceinline__ float fUnord(unsigned u) {
    return __uint_as_float((u & 0x80000000u) ? (u ^ 0x80000000u) : ~u);
}
// Vector reduction (sm_90+): one L2 message for 16 bytes instead of 4 scalars.
__device__ __forceinline__ void redAdd4(float* a, float x, float y, float z, float w) {
    asm volatile("red.global.add.v4.f32 [%0], {%1,%2,%3,%4};"
                 :: "l"(a), "f"(x), "f"(y), "f"(z), "f"(w) : "memory");
}

// ---------------- dtype detection (int64 vs int32 indices) ------------------
// Little-endian int64 values < 2^31 have zero high words at odd int32 slots.
__global__ void k_detect(const int* ei) {
    if (threadIdx.x == 0 && blockIdx.x == 0) {
        int z = 0;
        for (int i = 1; i < 256; i += 2) z += (ei[i] == 0);
        g_is64 = (z > 64) ? 1 : 0;
    }
}

__global__ void k_convert(const int* ei32, const int* b32) {
    int i = blockIdx.x * 256 + threadIdx.x;
    int is64 = g_is64;
    if (i < ETOT) {
        int s, d;
        if (i < EE) {
            if (is64) {
                const long long* e64 = (const long long*)ei32;
                s = (int)e64[i]; d = (int)e64[EE + i];
            } else {
                s = ei32[i]; d = ei32[EE + i];
            }
        } else {
            s = d = i - EE;   // self loops
        }
        g_src[i] = s; g_dst[i] = d;
    }
    if (i < NN) {
        g_batch[i] = is64 ? (int)((const long long*)b32)[i] : b32[i];
    }
}

// ---------------- embed: h0 = x @ W(5x64) + b -------------------------------
__global__ void k_embed(const float* __restrict__ x, const float* __restrict__ W,
                        const float* __restrict__ b) {
    __shared__ float sW[5 * 64];
    __shared__ float sb[64];
    int t = threadIdx.x;
    // FIX (R3 bug): 320-element tile needs a strided loop with 256 threads;
    // the old single conditional left sW[256..319] uninitialized.
    for (int i = t; i < 320; i += 256) sW[i] = W[i];
    if (t < 64) sb[t] = b[t];
    __syncthreads();
    int idx  = blockIdx.x * 256 + t;          // grid = NN*64/256 exactly
    int node = idx >> 6, c = idx & 63;
    float acc = sb[c];
#pragma unroll
    for (int k = 0; k < 5; k++) acc = fmaf(x[node * 5 + k], sW[k * 64 + c], acc);
    g_h0[idx] = acc;
}

// ---------------- per-layer scratch init ------------------------------------
__global__ void k_init_node() {
    int idx = blockIdx.x * 256 + threadIdx.x;  // NN*64
    g_hout[idx] = 0.f;
    if (idx < NN) { g_mU[idx] = 0u; g_den[idx] = 0.f; }
}

// ---------------- hlin = h0 @ W; alpha_s/d = hlin . a -----------------------
__global__ void k_gat_lin(const float* __restrict__ W,
                          const float* __restrict__ asrc,
                          const float* __restrict__ adst) {
    __shared__ float sW[64 * 64];
    __shared__ float sIn[4][64];
    __shared__ float sR0[4][64];
    __shared__ float sR1[4][64];
    int t = threadIdx.x;                       // 256 = 4 nodes x 64 cols
#pragma unroll 4
    for (int i = t; i < 4096; i += 256) sW[i] = W[i];
    int j = t >> 6, c = t & 63;
    int node = blockIdx.x * 4 + j;             // grid = NN/4 exactly
    sIn[j][c] = g_h0[node * 64 + c];
    __syncthreads();
    float acc = 0.f;
#pragma unroll
    for (int k = 0; k < 64; k++) acc = fmaf(sIn[j][k], sW[k * 64 + c], acc);
    g_hlin[node * 64 + c] = acc;
    sR0[j][c] = acc * asrc[c];
    sR1[j][c] = acc * adst[c];
    __syncthreads();
    if ((t & 32) == 0) {                       // lanes 0..31 of each node's warp pair
        float v0 = sR0[j][c] + sR0[j][c + 32];
        float v1 = sR1[j][c] + sR1[j][c + 32];
#pragma unroll
        for (int o = 16; o > 0; o >>= 1) {
            v0 += __shfl_down_sync(0xffffffffu, v0, o);
            v1 += __shfl_down_sync(0xffffffffu, v1, o);
        }
        if (c == 0) { g_as[node] = v0; g_ad[node] = v1; }
    }
}

// ---------------- edge pass 1: e = leaky_relu, segment max ------------------
__global__ void k_edge_max() {
    int e = blockIdx.x * 256 + threadIdx.x;
    if (e >= ETOT) return;
    int s = g_src[e], d = g_dst[e];
    float v = g_as[s] + g_ad[d];
    v = (v > 0.f) ? v : 0.2f * v;
    g_e[e] = v;
    atomicMax(&g_mU[d], fOrd(v));
}

// ---------------- edge pass 2: w = exp(e-m), segment sum --------------------
__global__ void k_edge_w() {
    int e = blockIdx.x * 256 + threadIdx.x;
    if (e >= ETOT) return;
    int d = g_dst[e];
    float m = fUnord(g_mU[d]);
    float w = expf(g_e[e] - m);
    g_w[e] = w;
    atomicAdd(&g_den[d], w);
}

// ---------------- edge pass 3: hout[dst] += alpha * hlin[src] ---------------
// 16 threads per edge, float4 per thread, v4 reductions.
__global__ void k_edge_agg() {
    int idx = blockIdx.x * 256 + threadIdx.x;  // grid = ETOT*16/256 exactly
    int e = idx >> 4;
    if (e >= ETOT) return;
    int l = idx & 15;
    int s = g_src[e], d = g_dst[e];
    float alpha = g_w[e] / (g_den[d] + 1e-16f);
    const float4 h = *(const float4*)&g_hlin[s * 64 + l * 4];
    redAdd4(&g_hout[d * 64 + l * 4], h.x * alpha, h.y * alpha, h.z * alpha, h.w * alpha);
}

// ---------------- bias (+ optional relu), write back to g_h0 ----------------
__global__ void k_bias_act(const float* __restrict__ b, int relu) {
    int idx = blockIdx.x * 256 + threadIdx.x;  // NN*64
    float v = g_hout[idx] + b[idx & 63];
    if (relu) v = fmaxf(v, 0.f);
    g_h0[idx] = v;
}

// ---------------- pooling ----------------------------------------------------
__global__ void k_pool_init() {
    int idx = blockIdx.x * 256 + threadIdx.x;  // GG*64
    g_psum[idx] = 0.f;
    g_pmax[idx] = 0u;
    if (idx < GG) g_cnt[idx] = 0;
}

__global__ void k_pool() {
    int idx = blockIdx.x * 256 + threadIdx.x;  // NN*64
    int node = idx >> 6, c = idx & 63;
    int g = g_batch[node];
    float v = g_h0[idx];
    atomicAdd(&g_psum[g * 64 + c], v);
    atomicMax(&g_pmax[g * 64 + c], fOrd(v));
    if (c == 0) atomicAdd(&g_cnt[g], 1);
}

__global__ void k_feat() {
    int idx = blockIdx.x * 256 + threadIdx.x;  // GG*128
    int g = idx >> 7, c = idx & 127;
    int n = g_cnt[g];
    float v;
    if (c < 64) v = g_psum[g * 64 + c] / fmaxf((float)n, 1.f);
    else        v = (n > 0) ? fUnord(g_pmax[g * 64 + (c - 64)]) : 0.f;
    g_feat[idx] = v;
}

// ---------------- MLP head ----------------------------------------------------
__global__ void k_mlp1(const float* __restrict__ W, const float* __restrict__ b) {
    __shared__ float sW[128 * 64];
    __shared__ float sIn[4][128];
    int t = threadIdx.x;                        // 256 = 4 graphs x 64 cols
    for (int i = t; i < 128 * 64; i += 256) sW[i] = W[i];
    int j = t >> 6, c = t & 63;
    int g = blockIdx.x * 4 + j;                 // grid = GG/4
    sIn[j][c]      = g_feat[g * 128 + c];
    sIn[j][c + 64] = g_feat[g * 128 + c + 64];
    __syncthreads();
    float acc = b[c];
#pragma unroll
    for (int k = 0; k < 128; k++) acc = fmaf(sIn[j][k], sW[k * 64 + c], acc);
    g_m1[g * 64 + c] = fmaxf(acc, 0.f);
}

__global__ void k_mlp2(const float* __restrict__ W, const float* __restrict__ b) {
    __shared__ float sW[64 * 32];
    __shared__ float sIn[8][64];
    int t = threadIdx.x;                        // 256 = 8 graphs x 32 cols
    for (int i = t; i < 64 * 32; i += 256) sW[i] = W[i];
    int j = t >> 5, c = t & 31;
    int g = blockIdx.x * 8 + j;                 // grid = GG/8
    sIn[j][c]      = g_m1[g * 64 + c];
    sIn[j][c + 32] = g_m1[g * 64 + c + 32];
    __syncthreads();
    float acc = b[c];
#pragma unroll
    for (int k = 0; k < 64; k++) acc = fmaf(sIn[j][k], sW[k * 32 + c], acc);
    g_m2[g * 32 + c] = fmaxf(acc, 0.f);
}

__global__ void k_mlp3(const float* __restrict__ W, const float* __restrict__ b,
                       float* __restrict__ out) {
    int g = blockIdx.x * 256 + threadIdx.x;     // grid = GG/256
    if (g >= GG) return;
    float acc = b[0];
#pragma unroll
    for (int k = 0; k < 32; k++) acc = fmaf(g_m2[g * 32 + k], W[k], acc);
    out[g] = acc;
}

// ---------------- launch ------------------------------------------------------
extern "C" void kernel_launch(void* const* d_in, const int* in_sizes, int n_in,
                              void* d_out, int out_size) {
    const float* x     = (const float*)d_in[0];
    const int*   ei    = (const int*)d_in[1];   // int32 or int64, detected on-device
    const int*   batch = (const int*)d_in[2];
    const float* embW  = (const float*)d_in[3];
    const float* embB  = (const float*)d_in[4];
    const float* g1W   = (const float*)d_in[5];
    const float* g1as  = (const float*)d_in[6];
    const float* g1ad  = (const float*)d_in[7];
    const float* g1b   = (const float*)d_in[8];
    const float* g2W   = (const float*)d_in[9];
    const float* g2as  = (const float*)d_in[10];
    const float* g2ad  = (const float*)d_in[11];
    const float* g2b   = (const float*)d_in[12];
    const float* fc1W  = (const float*)d_in[13];
    const float* fc1b  = (const float*)d_in[14];
    const float* fc2W  = (const float*)d_in[15];
    const float* fc2b  = (const float*)d_in[16];
    const float* fc3W  = (const float*)d_in[17];
    const float* fc3b  = (const float*)d_in[18];
    float* out = (float*)d_out;

    const int NH_BLOCKS  = (NN * 64) / 256;         // 50000
    const int ET_BLOCKS  = (ETOT + 255) / 256;      // 5469
    const int AGG_BLOCKS = (ETOT * 16) / 256;       // 87500

    k_detect<<<1, 32>>>(ei);
    k_convert<<<ET_BLOCKS, 256>>>(ei, batch);
    k_embed<<<NH_BLOCKS, 256>>>(x, embW, embB);

    // ---- GAT layer 1 ----
    k_init_node<<<NH_BLOCKS, 256>>>();
    k_gat_lin<<<NN / 4, 256>>>(g1W, g1as, g1ad);
    k_edge_max<<<ET_BLOCKS, 256>>>();
    k_edge_w<<<ET_BLOCKS, 256>>>();
    k_edge_agg<<<AGG_BLOCKS, 256>>>();
    k_bias_act<<<NH_BLOCKS, 256>>>(g1b, 1);

    // ---- GAT layer 2 ----
    k_init_node<<<NH_BLOCKS, 256>>>();
    k_gat_lin<<<NN / 4, 256>>>(g2W, g2as, g2ad);
    k_edge_max<<<ET_BLOCKS, 256>>>();
    k_edge_w<<<ET_BLOCKS, 256>>>();
    k_edge_agg<<<AGG_BLOCKS, 256>>>();
    k_bias_act<<<NH_BLOCKS, 256>>>(g2b, 0);

    // ---- pooling + MLP head ----
    k_pool_init<<<(GG * 64) / 256, 256>>>();
    k_pool<<<NH_BLOCKS, 256>>>();
    k_feat<<<(GG * 128) / 256, 256>>>();
    k_mlp1<<<GG / 4, 256>>>(fc1W, fc1b);
    k_mlp2<<<GG / 8, 256>>>(fc2W, fc2b);
    k_mlp3<<<(GG + 255) / 256, 256>>>(fc3W, fc3b, out);
}

// round 5
// speedup vs baseline: 2.1082x; 2.1082x over previous
#include <cuda_runtime.h>
#include <math.h>

#define NN   200000
#define EE   1200000
#define ETOT 1400000
#define GG   2048

// ---------------- scratch (device globals: no allocation allowed) ----------
__device__ __align__(16) float g_h0[NN * 64];    // node features (layer in/out)
__device__ __align__(16) float g_hlin[NN * 64];  // h @ W
__device__ float        g_as[NN];
__device__ float        g_ad[NN];
__device__ int          g_src[ETOT];
__device__ int          g_dst[ETOT];
__device__ int          g_deg[NN];
__device__ int          g_cursor[NN];
__device__ int          g_rowstart[NN];
__device__ int          g_col[ETOT];             // CSR by dst: src indices
__device__ int          g_total;
__device__ int          g_batch[NN];
__device__ __align__(16) float g_psum[GG * 64];
__device__ unsigned int g_pmax[GG * 64];
__device__ int          g_cnt[GG];
__device__ float        g_feat[GG * 128];
__device__ float        g_m1[GG * 64];
__device__ float        g_m2[GG * 32];
__device__ int          g_is64;

// ---------------- helpers ---------------------------------------------------
__device__ __forceinline__ unsigned fOrd(float f) {
    unsigned u = __float_as_uint(f);
    return (u & 0x80000000u) ? ~u : (u | 0x80000000u);
}
__device__ __forceinline__ float fUnord(unsigned u) {
    return __uint_as_float((u & 0x80000000u) ? (u ^ 0x80000000u) : ~u);
}

// ---------------- dtype detection (int64 vs int32 indices) ------------------
__global__ void k_detect(const int* ei) {
    if (threadIdx.x == 0 && blockIdx.x == 0) {
        int z = 0;
        for (int i = 1; i < 256; i += 2) z += (ei[i] == 0);
        g_is64 = (z > 64) ? 1 : 0;
    }
}

// ---------------- zero all accumulators / counters upfront ------------------
__global__ void k_zero() {
    int idx = blockIdx.x * 256 + threadIdx.x;        // covers NN
    if (idx < NN)      { g_deg[idx] = 0; g_cursor[idx] = 0; }
    if (idx < GG * 64) { g_psum[idx] = 0.f; g_pmax[idx] = 0u; }
    if (idx < GG)      g_cnt[idx] = 0;
    if (idx == 0)      g_total = 0;
}

// ---------------- convert indices + count degrees ---------------------------
__global__ void k_convert(const int* ei32, const int* b32) {
    int i = blockIdx.x * 256 + threadIdx.x;
    int is64 = g_is64;
    if (i < ETOT) {
        int s, d;
        if (i < EE) {
            if (is64) {
                const long long* e64 = (const long long*)ei32;
                s = (int)e64[i]; d = (int)e64[EE + i];
            } else {
                s = ei32[i]; d = ei32[EE + i];
            }
        } else {
            s = d = i - EE;   // self loops
        }
        g_src[i] = s; g_dst[i] = d;
        atomicAdd(&g_deg[d], 1);
    }
    if (i < NN) {
        g_batch[i] = is64 ? (int)((const long long*)b32)[i] : b32[i];
    }
}

// ---------------- row allocation: block scan + atomic base ------------------
__global__ void k_alloc() {
    __shared__ int sh[1024];
    __shared__ int sBase;
    int tid = threadIdx.x;
    int n = blockIdx.x * 1024 + tid;
    int d = (n < NN) ? g_deg[n] : 0;
    sh[tid] = d;
    __syncthreads();
#pragma unroll
    for (int o = 1; o < 1024; o <<= 1) {
        int x = (tid >= o) ? sh[tid - o] : 0;
        __syncthreads();
        sh[tid] += x;
        __syncthreads();
    }
    if (tid == 1023) sBase = atomicAdd(&g_total, sh[1023]);
    __syncthreads();
    if (n < NN) g_rowstart[n] = sBase + sh[tid] - d;
}

// ---------------- fill CSR ---------------------------------------------------
__global__ void k_fill() {
    int i = blockIdx.x * 256 + threadIdx.x;
    if (i >= ETOT) return;
    int d = g_dst[i];
    int slot = atomicAdd(&g_cursor[d], 1);
    g_col[g_rowstart[d] + slot] = g_src[i];
}

// ---------------- embed: h0 = x @ W(5x64) + b -------------------------------
__global__ void k_embed(const float* __restrict__ x, const float* __restrict__ W,
                        const float* __restrict__ b) {
    __shared__ float sW[5 * 64];
    __shared__ float sb[64];
    int t = threadIdx.x;
    for (int i = t; i < 320; i += 256) sW[i] = W[i];
    if (t < 64) sb[t] = b[t];
    __syncthreads();
    int idx  = blockIdx.x * 256 + t;          // grid = NN*64/256 exactly
    int node = idx >> 6, c = idx & 63;
    float acc = sb[c];
#pragma unroll
    for (int k = 0; k < 5; k++) acc = fmaf(x[node * 5 + k], sW[k * 64 + c], acc);
    g_h0[idx] = acc;
}

// ---------------- hlin = h0 @ W; alpha_s/d = hlin . a -----------------------
// Register-tiled: 256 threads compute 64 nodes x 64 cols (4x4 per thread).
__global__ void __launch_bounds__(256) k_gat_lin(const float* __restrict__ W,
                          const float* __restrict__ asrc,
                          const float* __restrict__ adst) {
    __shared__ float sW[64 * 64];
    __shared__ float sIn[64 * 68];    // transposed [k][node], stride 68 (16B-aligned rows)
    __shared__ float sA[64], sD[64];
    int t = threadIdx.x;
    int base = blockIdx.x * 64;       // grid = NN/64 exactly
#pragma unroll 4
    for (int i = t; i < 4096; i += 256) sW[i] = W[i];
#pragma unroll 4
    for (int i = t; i < 4096; i += 256) {
        int node = i >> 6, k = i & 63;
        sIn[k * 68 + node] = g_h0[(base + node) * 64 + k];
    }
    if (t < 64)             sA[t]      = asrc[t];
    else if (t < 128)       sD[t - 64] = adst[t - 64];
    __syncthreads();

    int tx = t & 15, ty = t >> 4;     // tx: col quad, ty: node quad
    float acc[4][4] = {};
#pragma unroll 8
    for (int k = 0; k < 64; k++) {
        float4 wv = *(const float4*)&sW[k * 64 + tx * 4];
        float4 hv = *(const float4*)&sIn[k * 68 + ty * 4];
#pragma unroll
        for (int i = 0; i < 4; i++) {
            float h = (i == 0) ? hv.x : (i == 1) ? hv.y : (i == 2) ? hv.z : hv.w;
            acc[i][0] = fmaf(h, wv.x, acc[i][0]);
            acc[i][1] = fmaf(h, wv.y, acc[i][1]);
            acc[i][2] = fmaf(h, wv.z, acc[i][2]);
            acc[i][3] = fmaf(h, wv.w, acc[i][3]);
        }
    }
    float a0 = sA[tx * 4], a1 = sA[tx * 4 + 1], a2 = sA[tx * 4 + 2], a3 = sA[tx * 4 + 3];
    float d0 = sD[tx * 4], d1 = sD[tx * 4 + 1], d2 = sD[tx * 4 + 2], d3 = sD[tx * 4 + 3];
#pragma unroll
    for (int i = 0; i < 4; i++) {
        int node = base + ty * 4 + i;
        float4 v = make_float4(acc[i][0], acc[i][1], acc[i][2], acc[i][3]);
        *(float4*)&g_hlin[node * 64 + tx * 4] = v;
        float ps = v.x * a0 + v.y * a1 + v.z * a2 + v.w * a3;
        float pd = v.x * d0 + v.y * d1 + v.z * d2 + v.w * d3;
#pragma unroll
        for (int o = 8; o > 0; o >>= 1) {
            ps += __shfl_down_sync(0xffffffffu, ps, o, 16);
            pd += __shfl_down_sync(0xffffffffu, pd, o, 16);
        }
        if (tx == 0) { g_as[node] = ps; g_ad[node] = pd; }
    }
}

// ---------------- fused per-node aggregation (online softmax) ---------------
// One warp per node: no atomics, coalesced 256B gathers of hlin[src].
__global__ void k_node_agg(const float* __restrict__ b, int relu) {
    int warp = (blockIdx.x * 256 + threadIdx.x) >> 5;   // grid = NN/8 blocks of 256
    int lane = threadIdx.x & 31;
    if (warp >= NN) return;
    int n     = warp;
    int start = g_rowstart[n];
    int deg   = g_deg[n];
    float adn = g_ad[n];

    float m = -INFINITY, den = 0.f, acc0 = 0.f, acc1 = 0.f;
    for (int base = 0; base < deg; base += 32) {
        int cnt = min(32, deg - base);
        int s = 0;
        float e = -INFINITY;
        if (lane < cnt) {
            s = g_col[start + base + lane];
            float v = g_as[s] + adn;
            e = (v > 0.f) ? v : 0.2f * v;
        }
        float mloc = e;
#pragma unroll
        for (int o = 16; o > 0; o >>= 1)
            mloc = fmaxf(mloc, __shfl_xor_sync(0xffffffffu, mloc, o));
        float newm  = fmaxf(m, mloc);
        float scale = expf(m - newm);          // 0 on first chunk (m=-inf)
        den *= scale; acc0 *= scale; acc1 *= scale;
        float w = (lane < cnt) ? expf(e - newm) : 0.f;
        float wsum = w;
#pragma unroll
        for (int o = 16; o > 0; o >>= 1)
            wsum += __shfl_xor_sync(0xffffffffu, wsum, o);
        den += wsum;
        m = newm;
        for (int j = 0; j < cnt; j++) {
            float wj = __shfl_sync(0xffffffffu, w, j);
            int   sj = __shfl_sync(0xffffffffu, s, j);
            const float* hp = &g_hlin[sj * 64];
            acc0 = fmaf(wj, hp[lane],      acc0);
            acc1 = fmaf(wj, hp[lane + 32], acc1);
        }
    }
    float inv = 1.f / (den + 1e-16f);
    float o0 = acc0 * inv + b[lane];
    float o1 = acc1 * inv + b[lane + 32];
    if (relu) { o0 = fmaxf(o0, 0.f); o1 = fmaxf(o1, 0.f); }
    g_h0[n * 64 + lane]      = o0;
    g_h0[n * 64 + 32 + lane] = o1;
}

// ---------------- pooling: exploit sorted batch, run-length local accum -----
__global__ void k_pool() {
    int t = threadIdx.x;
    int c = t & 63, j = t >> 2 >> 4;           // j = t>>6
    int n0 = blockIdx.x * 256 + (t >> 6) * 64; // each of 4 groups scans 64 nodes
    float lsum = 0.f, lmax = -INFINITY;
    int lcnt = 0, curg = -1;
    (void)j;
    for (int i = 0; i < 64; i++) {
        int n = n0 + i;
        if (n >= NN) break;
        int g = g_batch[n];
        if (g != curg) {
            if (curg >= 0) {
                atomicAdd(&g_psum[curg * 64 + c], lsum);
                atomicMax(&g_pmax[curg * 64 + c], fOrd(lmax));
                if (c == 0) atomicAdd(&g_cnt[curg], lcnt);
            }
            curg = g; lsum = 0.f; lmax = -INFINITY; lcnt = 0;
        }
        float v = g_h0[n * 64 + c];
        lsum += v; lmax = fmaxf(lmax, v); lcnt++;
    }
    if (curg >= 0) {
        atomicAdd(&g_psum[curg * 64 + c], lsum);
        atomicMax(&g_pmax[curg * 64 + c], fOrd(lmax));
        if (c == 0) atomicAdd(&g_cnt[curg], lcnt);
    }
}

__global__ void k_feat() {
    int idx = blockIdx.x * 256 + threadIdx.x;  // GG*128
    int g = idx >> 7, c = idx & 127;
    int n = g_cnt[g];
    float v;
    if (c < 64) v = g_psum[g * 64 + c] / fmaxf((float)n, 1.f);
    else        v = (n > 0) ? fUnord(g_pmax[g * 64 + (c - 64)]) : 0.f;
    g_feat[idx] = v;
}

// ---------------- MLP head ---------------------------------------------------
__global__ void k_mlp1(const float* __restrict__ W, const float* __restrict__ b) {
    __shared__ float sW[128 * 64];
    __shared__ float sIn[4][128];
    int t = threadIdx.x;                        // 256 = 4 graphs x 64 cols
    for (int i = t; i < 128 * 64; i += 256) sW[i] = W[i];
    int j = t >> 6, c = t & 63;
    int g = blockIdx.x * 4 + j;                 // grid = GG/4
    sIn[j][c]      = g_feat[g * 128 + c];
    sIn[j][c + 64] = g_feat[g * 128 + c + 64];
    __syncthreads();
    float acc = b[c];
#pragma unroll
    for (int k = 0; k < 128; k++) acc = fmaf(sIn[j][k], sW[k * 64 + c], acc);
    g_m1[g * 64 + c] = fmaxf(acc, 0.f);
}

__global__ void k_mlp2(const float* __restrict__ W, const float* __restrict__ b) {
    __shared__ float sW[64 * 32];
    __shared__ float sIn[8][64];
    int t = threadIdx.x;                        // 256 = 8 graphs x 32 cols
    for (int i = t; i < 64 * 32; i += 256) sW[i] = W[i];
    int j = t >> 5, c = t & 31;
    int g = blockIdx.x * 8 + j;                 // grid = GG/8
    sIn[j][c]      = g_m1[g * 64 + c];
    sIn[j][c + 32] = g_m1[g * 64 + c + 32];
    __syncthreads();
    float acc = b[c];
#pragma unroll
    for (int k = 0; k < 64; k++) acc = fmaf(sIn[j][k], sW[k * 32 + c], acc);
    g_m2[g * 32 + c] = fmaxf(acc, 0.f);
}

__global__ void k_mlp3(const float* __restrict__ W, const float* __restrict__ b,
                       float* __restrict__ out) {
    int g = blockIdx.x * 256 + threadIdx.x;     // grid covers GG
    if (g >= GG) return;
    float acc = b[0];
#pragma unroll
    for (int k = 0; k < 32; k++) acc = fmaf(g_m2[g * 32 + k], W[k], acc);
    out[g] = acc;
}

// ---------------- launch ------------------------------------------------------
extern "C" void kernel_launch(void* const* d_in, const int* in_sizes, int n_in,
                              void* d_out, int out_size) {
    const float* x     = (const float*)d_in[0];
    const int*   ei    = (const int*)d_in[1];
    const int*   batch = (const int*)d_in[2];
    const float* embW  = (const float*)d_in[3];
    const float* embB  = (const float*)d_in[4];
    const float* g1W   = (const float*)d_in[5];
    const float* g1as  = (const float*)d_in[6];
    const float* g1ad  = (const float*)d_in[7];
    const float* g1b   = (const float*)d_in[8];
    const float* g2W   = (const float*)d_in[9];
    const float* g2as  = (const float*)d_in[10];
    const float* g2ad  = (const float*)d_in[11];
    const float* g2b   = (const float*)d_in[12];
    const float* fc1W  = (const float*)d_in[13];
    const float* fc1b  = (const float*)d_in[14];
    const float* fc2W  = (const float*)d_in[15];
    const float* fc2b  = (const float*)d_in[16];
    const float* fc3W  = (const float*)d_in[17];
    const float* fc3b  = (const float*)d_in[18];
    float* out = (float*)d_out;

    const int NH_BLOCKS = (NN * 64) / 256;          // 50000
    const int ET_BLOCKS = (ETOT + 255) / 256;       // 5469
    const int N_BLOCKS  = (NN + 255) / 256;         // 782

    k_detect<<<1, 32>>>(ei);
    k_zero<<<N_BLOCKS, 256>>>();
    k_convert<<<ET_BLOCKS, 256>>>(ei, batch);
    k_alloc<<<(NN + 1023) / 1024, 1024>>>();
    k_fill<<<ET_BLOCKS, 256>>>();
    k_embed<<<NH_BLOCKS, 256>>>(x, embW, embB);

    // ---- GAT layer 1 ----
    k_gat_lin<<<NN / 64, 256>>>(g1W, g1as, g1ad);
    k_node_agg<<<NN / 8, 256>>>(g1b, 1);

    // ---- GAT layer 2 ----
    k_gat_lin<<<NN / 64, 256>>>(g2W, g2as, g2ad);
    k_node_agg<<<NN / 8, 256>>>(g2b, 0);

    // ---- pooling + MLP head ----
    k_pool<<<N_BLOCKS, 256>>>();
    k_feat<<<(GG * 128) / 256, 256>>>();
    k_mlp1<<<GG / 4, 256>>>(fc1W, fc1b);
    k_mlp2<<<GG / 8, 256>>>(fc2W, fc2b);
    k_mlp3<<<(GG + 255) / 256, 256>>>(fc3W, fc3b, out);
}

// round 6
// speedup vs baseline: 2.2282x; 1.0569x over previous
#include <cuda_runtime.h>
#include <math.h>

#define NN   200000
#define EE   1200000
#define ETOT 1400000
#define GG   2048

// ---------------- scratch (device globals: no allocation allowed) ----------
__device__ __align__(16) float g_h0[NN * 64];    // node features (layer in/out)
__device__ __align__(16) float g_hlin[NN * 64];  // h @ W
__device__ float        g_as[NN];
__device__ float        g_ad[NN];
__device__ int          g_src[ETOT];
__device__ int          g_dst[ETOT];
__device__ int          g_deg[NN];
__device__ int          g_cursor[NN];
__device__ int          g_rowstart[NN];
__device__ int          g_col[ETOT];             // CSR by dst: src indices
__device__ int          g_total;
__device__ int          g_batch[NN];
__device__ __align__(16) float g_psum[GG * 64];
__device__ unsigned int g_pmax[GG * 64];
__device__ int          g_cnt[GG];
__device__ float        g_feat[GG * 128];
__device__ float        g_m1[GG * 64];
__device__ float        g_m2[GG * 32];
__device__ int          g_is64;

// ---------------- helpers ---------------------------------------------------
__device__ __forceinline__ unsigned fOrd(float f) {
    unsigned u = __float_as_uint(f);
    return (u & 0x80000000u) ? ~u : (u | 0x80000000u);
}
__device__ __forceinline__ float fUnord(unsigned u) {
    return __uint_as_float((u & 0x80000000u) ? (u ^ 0x80000000u) : ~u);
}

// ---------------- zero scratch + dtype detection -----------------------------
__global__ void k_zero_detect(const int* ei) {
    int idx = blockIdx.x * 256 + threadIdx.x;        // covers NN (> GG*64)
    if (idx < NN)      { g_deg[idx] = 0; g_cursor[idx] = 0; }
    if (idx < GG * 64) { g_psum[idx] = 0.f; g_pmax[idx] = 0u; }
    if (idx < GG)      g_cnt[idx] = 0;
    if (idx == 0) {
        g_total = 0;
        int z = 0;
        for (int i = 1; i < 256; i += 2) z += (ei[i] == 0);
        g_is64 = (z > 64) ? 1 : 0;
    }
}

// ---------------- convert indices + count degrees ---------------------------
__global__ void k_convert(const int* ei32, const int* b32) {
    int i = blockIdx.x * 256 + threadIdx.x;
    int is64 = g_is64;
    if (i < ETOT) {
        int s, d;
        if (i < EE) {
            if (is64) {
                const long long* e64 = (const long long*)ei32;
                s = (int)e64[i]; d = (int)e64[EE + i];
            } else {
                s = ei32[i]; d = ei32[EE + i];
            }
        } else {
            s = d = i - EE;   // self loops
        }
        g_src[i] = s; g_dst[i] = d;
        atomicAdd(&g_deg[d], 1);
    }
    if (i < NN) {
        g_batch[i] = is64 ? (int)((const long long*)b32)[i] : b32[i];
    }
}

// ---------------- row allocation: warp-shuffle scan + atomic base -----------
__global__ void k_alloc() {
    __shared__ int warpsum[32];
    __shared__ int sBase;
    int tid  = threadIdx.x;
    int n    = blockIdx.x * 1024 + tid;
    int lane = tid & 31, wid = tid >> 5;
    int d = (n < NN) ? g_deg[n] : 0;
    int x = d;                                  // inclusive warp scan
#pragma unroll
    for (int o = 1; o < 32; o <<= 1) {
        int y = __shfl_up_sync(0xffffffffu, x, o);
        if (lane >= o) x += y;
    }
    if (lane == 31) warpsum[wid] = x;
    __syncthreads();
    if (wid == 0) {
        int v = warpsum[lane];
#pragma unroll
        for (int o = 1; o < 32; o <<= 1) {
            int y = __shfl_up_sync(0xffffffffu, v, o);
            if (lane >= o) v += y;
        }
        if (lane == 31) sBase = atomicAdd(&g_total, v);
        warpsum[lane] = v;                      // inclusive warp totals
    }
    __syncthreads();
    int pre = ((wid > 0) ? warpsum[wid - 1] : 0) + x - d;   // exclusive prefix
    if (n < NN) g_rowstart[n] = sBase + pre;
}

// ---------------- fill CSR ---------------------------------------------------
__global__ void k_fill() {
    int i = blockIdx.x * 256 + threadIdx.x;
    if (i >= ETOT) return;
    int d = g_dst[i];
    int slot = atomicAdd(&g_cursor[d], 1);
    g_col[g_rowstart[d] + slot] = g_src[i];
}

// ---------------- embed: h0 = x @ W(5x64) + b -------------------------------
__global__ void k_embed(const float* __restrict__ x, const float* __restrict__ W,
                        const float* __restrict__ b) {
    __shared__ float sW[5 * 64];
    __shared__ float sb[64];
    int t = threadIdx.x;
    for (int i = t; i < 320; i += 256) sW[i] = W[i];
    if (t < 64) sb[t] = b[t];
    __syncthreads();
    int idx  = blockIdx.x * 256 + t;          // grid = NN*64/256 exactly
    int node = idx >> 6, c = idx & 63;
    float acc = sb[c];
#pragma unroll
    for (int k = 0; k < 5; k++) acc = fmaf(x[node * 5 + k], sW[k * 64 + c], acc);
    g_h0[idx] = acc;
}

// ---------------- hlin = h0 @ W; alpha_s/d = hlin . a -----------------------
// Register-tiled: 256 threads compute 64 nodes x 64 cols (4x4 per thread).
__global__ void __launch_bounds__(256) k_gat_lin(const float* __restrict__ W,
                          const float* __restrict__ asrc,
                          const float* __restrict__ adst) {
    __shared__ float sW[64 * 64];
    __shared__ float sIn[64 * 68];    // transposed [k][node], stride 68
    __shared__ float sA[64], sD[64];
    int t = threadIdx.x;
    int base = blockIdx.x * 64;       // grid = NN/64 exactly
#pragma unroll 4
    for (int i = t; i < 4096; i += 256) sW[i] = W[i];
#pragma unroll 4
    for (int i = t; i < 4096; i += 256) {
        int node = i >> 6, k = i & 63;
        sIn[k * 68 + node] = g_h0[(base + node) * 64 + k];
    }
    if (t < 64)             sA[t]      = asrc[t];
    else if (t < 128)       sD[t - 64] = adst[t - 64];
    __syncthreads();

    int tx = t & 15, ty = t >> 4;     // tx: col quad, ty: node quad
    float acc[4][4] = {};
#pragma unroll 8
    for (int k = 0; k < 64; k++) {
        float4 wv = *(const float4*)&sW[k * 64 + tx * 4];
        float4 hv = *(const float4*)&sIn[k * 68 + ty * 4];
#pragma unroll
        for (int i = 0; i < 4; i++) {
            float h = (i == 0) ? hv.x : (i == 1) ? hv.y : (i == 2) ? hv.z : hv.w;
            acc[i][0] = fmaf(h, wv.x, acc[i][0]);
            acc[i][1] = fmaf(h, wv.y, acc[i][1]);
            acc[i][2] = fmaf(h, wv.z, acc[i][2]);
            acc[i][3] = fmaf(h, wv.w, acc[i][3]);
        }
    }
    float a0 = sA[tx * 4], a1 = sA[tx * 4 + 1], a2 = sA[tx * 4 + 2], a3 = sA[tx * 4 + 3];
    float d0 = sD[tx * 4], d1 = sD[tx * 4 + 1], d2 = sD[tx * 4 + 2], d3 = sD[tx * 4 + 3];
#pragma unroll
    for (int i = 0; i < 4; i++) {
        int node = base + ty * 4 + i;
        float4 v = make_float4(acc[i][0], acc[i][1], acc[i][2], acc[i][3]);
        *(float4*)&g_hlin[node * 64 + tx * 4] = v;
        float ps = v.x * a0 + v.y * a1 + v.z * a2 + v.w * a3;
        float pd = v.x * d0 + v.y * d1 + v.z * d2 + v.w * d3;
#pragma unroll
        for (int o = 8; o > 0; o >>= 1) {
            ps += __shfl_down_sync(0xffffffffu, ps, o, 16);
            pd += __shfl_down_sync(0xffffffffu, pd, o, 16);
        }
        if (tx == 0) { g_as[node] = ps; g_ad[node] = pd; }
    }
}

// ---------------- fused per-node aggregation (online softmax) ---------------
// One warp per node; lane owns columns {2*lane, 2*lane+1} (float2 gathers).
// Edge loop unrolled x4 -> 4 independent gathers in flight (MLP=4).
__global__ void __launch_bounds__(256) k_node_agg(const float* __restrict__ b, int relu) {
    int warp = (blockIdx.x * 256 + threadIdx.x) >> 5;   // grid = NN/8 blocks
    int lane = threadIdx.x & 31;
    if (warp >= NN) return;
    int n     = warp;
    int start = g_rowstart[n];
    int deg   = g_deg[n];
    float adn = g_ad[n];
    const float2* hb = (const float2*)g_hlin;

    float m = -INFINITY, den = 0.f;
    float ax = 0.f, ay = 0.f;
    for (int base = 0; base < deg; base += 32) {
        int cnt = min(32, deg - base);
        int s = 0;
        float e = -INFINITY;
        if (lane < cnt) {
            s = __ldg(&g_col[start + base + lane]);
            float v = __ldg(&g_as[s]) + adn;
            e = (v > 0.f) ? v : 0.2f * v;
        }
        float mloc = e;
#pragma unroll
        for (int o = 16; o > 0; o >>= 1)
            mloc = fmaxf(mloc, __shfl_xor_sync(0xffffffffu, mloc, o));
        float newm  = fmaxf(m, mloc);
        float scale = expf(m - newm);          // 0 on first chunk (m=-inf)
        den *= scale; ax *= scale; ay *= scale;
        float w = (lane < cnt) ? expf(e - newm) : 0.f;
        float wsum = w;
#pragma unroll
        for (int o = 16; o > 0; o >>= 1)
            wsum += __shfl_xor_sync(0xffffffffu, wsum, o);
        den += wsum;
        m = newm;

        int j = 0;
        for (; j + 4 <= cnt; j += 4) {
            int   s0 = __shfl_sync(0xffffffffu, s, j);
            int   s1 = __shfl_sync(0xffffffffu, s, j + 1);
            int   s2 = __shfl_sync(0xffffffffu, s, j + 2);
            int   s3 = __shfl_sync(0xffffffffu, s, j + 3);
            float w0 = __shfl_sync(0xffffffffu, w, j);
            float w1 = __shfl_sync(0xffffffffu, w, j + 1);
            float w2 = __shfl_sync(0xffffffffu, w, j + 2);
            float w3 = __shfl_sync(0xffffffffu, w, j + 3);
            float2 h0 = __ldg(&hb[s0 * 32 + lane]);
            float2 h1 = __ldg(&hb[s1 * 32 + lane]);
            float2 h2 = __ldg(&hb[s2 * 32 + lane]);
            float2 h3 = __ldg(&hb[s3 * 32 + lane]);
            ax = fmaf(w0, h0.x, ax); ay = fmaf(w0, h0.y, ay);
            ax = fmaf(w1, h1.x, ax); ay = fmaf(w1, h1.y, ay);
            ax = fmaf(w2, h2.x, ax); ay = fmaf(w2, h2.y, ay);
            ax = fmaf(w3, h3.x, ax); ay = fmaf(w3, h3.y, ay);
        }
        for (; j < cnt; j++) {
            int   sj = __shfl_sync(0xffffffffu, s, j);
            float wj = __shfl_sync(0xffffffffu, w, j);
            float2 h = __ldg(&hb[sj * 32 + lane]);
            ax = fmaf(wj, h.x, ax); ay = fmaf(wj, h.y, ay);
        }
    }
    float inv = 1.f / (den + 1e-16f);
    float o0 = ax * inv + b[2 * lane];
    float o1 = ay * inv + b[2 * lane + 1];
    if (relu) { o0 = fmaxf(o0, 0.f); o1 = fmaxf(o1, 0.f); }
    ((float2*)g_h0)[n * 32 + lane] = make_float2(o0, o1);
}

// ---------------- pooling: sorted batch, run-length, pipelined reads --------
__global__ void k_pool() {
    int t = threadIdx.x;
    int c = t & 63;
    int n0 = blockIdx.x * 128 + (t >> 6) * 32;   // 4 groups x 32 nodes / block
    if (n0 >= NN) return;
    int nend = min(n0 + 32, NN);

    int   rg   = g_batch[n0];                    // current run's graph
    float v    = g_h0[n0 * 64 + c];
    float lsum = 0.f, lmax = -INFINITY;
    int   lcnt = 0;
    for (int n = n0; n < nend; n++) {
        int   gnext = (n + 1 < nend) ? g_batch[n + 1] : -1;
        float vnext = (n + 1 < nend) ? g_h0[(n + 1) * 64 + c] : 0.f;
        lsum += v; lmax = fmaxf(lmax, v); lcnt++;
        if (gnext != rg) {
            atomicAdd(&g_psum[rg * 64 + c], lsum);
            atomicMax(&g_pmax[rg * 64 + c], fOrd(lmax));
            if (c == 0) atomicAdd(&g_cnt[rg], lcnt);
            rg = gnext; lsum = 0.f; lmax = -INFINITY; lcnt = 0;
        }
        v = vnext;
    }
}

__global__ void k_feat() {
    int idx = blockIdx.x * 256 + threadIdx.x;  // GG*128
    int g = idx >> 7, c = idx & 127;
    int n = g_cnt[g];
    float v;
    if (c < 64) v = g_psum[g * 64 + c] / fmaxf((float)n, 1.f);
    else        v = (n > 0) ? fUnord(g_pmax[g * 64 + (c - 64)]) : 0.f;
    g_feat[idx] = v;
}

// ---------------- MLP head ---------------------------------------------------
__global__ void k_mlp1(const float* __restrict__ W, const float* __restrict__ b) {
    __shared__ float sW[128 * 64];
    __shared__ float sIn[4][128];
    int t = threadIdx.x;                        // 256 = 4 graphs x 64 cols
    for (int i = t; i < 128 * 64; i += 256) sW[i] = W[i];
    int j = t >> 6, c = t & 63;
    int g = blockIdx.x * 4 + j;                 // grid = GG/4
    sIn[j][c]      = g_feat[g * 128 + c];
    sIn[j][c + 64] = g_feat[g * 128 + c + 64];
    __syncthreads();
    float acc = b[c];
#pragma unroll
    for (int k = 0; k < 128; k++) acc = fmaf(sIn[j][k], sW[k * 64 + c], acc);
    g_m1[g * 64 + c] = fmaxf(acc, 0.f);
}

__global__ void k_mlp2(const float* __restrict__ W, const float* __restrict__ b) {
    __shared__ float sW[64 * 32];
    __shared__ float sIn[8][64];
    int t = threadIdx.x;                        // 256 = 8 graphs x 32 cols
    for (int i = t; i < 64 * 32; i += 256) sW[i] = W[i];
    int j = t >> 5, c = t & 31;
    int g = blockIdx.x * 8 + j;                 // grid = GG/8
    sIn[j][c]      = g_m1[g * 64 + c];
    sIn[j][c + 32] = g_m1[g * 64 + c + 32];
    __syncthreads();
    float acc = b[c];
#pragma unroll
    for (int k = 0; k < 64; k++) acc = fmaf(sIn[j][k], sW[k * 32 + c], acc);
    g_m2[g * 32 + c] = fmaxf(acc, 0.f);
}

__global__ void k_mlp3(const float* __restrict__ W, const float* __restrict__ b,
                       float* __restrict__ out) {
    int g = blockIdx.x * 256 + threadIdx.x;     // grid covers GG
    if (g >= GG) return;
    float acc = b[0];
#pragma unroll
    for (int k = 0; k < 32; k++) acc = fmaf(g_m2[g * 32 + k], W[k], acc);
    out[g] = acc;
}

// ---------------- launch ------------------------------------------------------
extern "C" void kernel_launch(void* const* d_in, const int* in_sizes, int n_in,
                              void* d_out, int out_size) {
    const float* x     = (const float*)d_in[0];
    const int*   ei    = (const int*)d_in[1];
    const int*   batch = (const int*)d_in[2];
    const float* embW  = (const float*)d_in[3];
    const float* embB  = (const float*)d_in[4];
    const float* g1W   = (const float*)d_in[5];
    const float* g1as  = (const float*)d_in[6];
    const float* g1ad  = (const float*)d_in[7];
    const float* g1b   = (const float*)d_in[8];
    const float* g2W   = (const float*)d_in[9];
    const float* g2as  = (const float*)d_in[10];
    const float* g2ad  = (const float*)d_in[11];
    const float* g2b   = (const float*)d_in[12];
    const float* fc1W  = (const float*)d_in[13];
    const float* fc1b  = (const float*)d_in[14];
    const float* fc2W  = (const float*)d_in[15];
    const float* fc2b  = (const float*)d_in[16];
    const float* fc3W  = (const float*)d_in[17];
    const float* fc3b  = (const float*)d_in[18];
    float* out = (float*)d_out;

    const int NH_BLOCKS = (NN * 64) / 256;          // 50000
    const int ET_BLOCKS = (ETOT + 255) / 256;       // 5469
    const int N_BLOCKS  = (NN + 255) / 256;         // 782

    k_zero_detect<<<N_BLOCKS, 256>>>(ei);
    k_convert<<<ET_BLOCKS, 256>>>(ei, batch);
    k_alloc<<<(NN + 1023) / 1024, 1024>>>();
    k_fill<<<ET_BLOCKS, 256>>>();
    k_embed<<<NH_BLOCKS, 256>>>(x, embW, embB);

    // ---- GAT layer 1 ----
    k_gat_lin<<<NN / 64, 256>>>(g1W, g1as, g1ad);
    k_node_agg<<<NN / 8, 256>>>(g1b, 1);

    // ---- GAT layer 2 ----
    k_gat_lin<<<NN / 64, 256>>>(g2W, g2as, g2ad);
    k_node_agg<<<NN / 8, 256>>>(g2b, 0);

    // ---- pooling + MLP head ----
    k_pool<<<(NN + 127) / 128, 256>>>();
    k_feat<<<(GG * 128) / 256, 256>>>();
    k_mlp1<<<GG / 4, 256>>>(fc1W, fc1b);
    k_mlp2<<<GG / 8, 256>>>(fc2W, fc2b);
    k_mlp3<<<(GG + 255) / 256, 256>>>(fc3W, fc3b, out);
}

// round 7
// speedup vs baseline: 2.5257x; 1.1335x over previous
#include <cuda_runtime.h>
#include <math.h>

#define NN   200000
#define EE   1200000
#define ETOT 1400000
#define GG   2048

// ---------------- scratch (device globals: no allocation allowed) ----------
__device__ __align__(16) float g_h0[NN * 64];    // node features (layer output)
__device__ __align__(16) float g_hlin[NN * 64];  // h @ W
__device__ float        g_as[NN];
__device__ float        g_ad[NN];
__device__ int          g_src[ETOT];
__device__ int          g_dst[ETOT];
__device__ int          g_slot[ETOT];            // per-edge slot within dst row
__device__ int          g_deg[NN];
__device__ int          g_rowstart[NN];
__device__ int          g_col[ETOT];             // CSR by dst: src indices
__device__ int          g_total;
__device__ int          g_batch[NN];
__device__ __align__(16) float g_psum[GG * 64];
__device__ unsigned int g_pmax[GG * 64];
__device__ int          g_cnt[GG];
__device__ int          g_is64;

// ---------------- helpers ---------------------------------------------------
__device__ __forceinline__ unsigned fOrd(float f) {
    unsigned u = __float_as_uint(f);
    return (u & 0x80000000u) ? ~u : (u | 0x80000000u);
}
__device__ __forceinline__ float fUnord(unsigned u) {
    return __uint_as_float((u & 0x80000000u) ? (u ^ 0x80000000u) : ~u);
}

// ---------------- zero scratch + dtype detection -----------------------------
__global__ void k_zero_detect(const int* ei) {
    int idx = blockIdx.x * 256 + threadIdx.x;        // covers NN (> GG*64)
    if (idx < NN)      g_deg[idx] = 0;
    if (idx < GG * 64) { g_psum[idx] = 0.f; g_pmax[idx] = 0u; }
    if (idx < GG)      g_cnt[idx] = 0;
    if (idx == 0) {
        g_total = 0;
        int z = 0;
        for (int i = 1; i < 256; i += 2) z += (ei[i] == 0);
        g_is64 = (z > 64) ? 1 : 0;
    }
}

// ---------------- convert indices + count degrees (slot = old count) --------
__global__ void k_convert(const int* ei32, const int* b32) {
    int i = blockIdx.x * 256 + threadIdx.x;
    int is64 = g_is64;
    if (i < ETOT) {
        int s, d;
        if (i < EE) {
            if (is64) {
                const long long* e64 = (const long long*)ei32;
                s = (int)e64[i]; d = (int)e64[EE + i];
            } else {
                s = ei32[i]; d = ei32[EE + i];
            }
        } else {
            s = d = i - EE;   // self loops
        }
        g_src[i] = s; g_dst[i] = d;
        g_slot[i] = atomicAdd(&g_deg[d], 1);
    }
    if (i < NN) {
        g_batch[i] = is64 ? (int)((const long long*)b32)[i] : b32[i];
    }
}

// ---------------- row allocation: warp-shuffle scan + atomic base -----------
__global__ void k_alloc() {
    __shared__ int warpsum[32];
    __shared__ int sBase;
    int tid  = threadIdx.x;
    int n    = blockIdx.x * 1024 + tid;
    int lane = tid & 31, wid = tid >> 5;
    int d = (n < NN) ? g_deg[n] : 0;
    int x = d;                                  // inclusive warp scan
#pragma unroll
    for (int o = 1; o < 32; o <<= 1) {
        int y = __shfl_up_sync(0xffffffffu, x, o);
        if (lane >= o) x += y;
    }
    if (lane == 31) warpsum[wid] = x;
    __syncthreads();
    if (wid == 0) {
        int v = warpsum[lane];
#pragma unroll
        for (int o = 1; o < 32; o <<= 1) {
            int y = __shfl_up_sync(0xffffffffu, v, o);
            if (lane >= o) v += y;
        }
        if (lane == 31) sBase = atomicAdd(&g_total, v);
        warpsum[lane] = v;
    }
    __syncthreads();
    int pre = ((wid > 0) ? warpsum[wid - 1] : 0) + x - d;   // exclusive prefix
    if (n < NN) g_rowstart[n] = sBase + pre;
}

// ---------------- fill CSR (no atomics: slot precomputed) -------------------
__global__ void k_fill() {
    int i = blockIdx.x * 256 + threadIdx.x;
    if (i >= ETOT) return;
    int d = g_dst[i];
    g_col[g_rowstart[d] + g_slot[i]] = g_src[i];
}

// ---------------- hlin = h @ W; alpha_s/d = hlin . a ------------------------
// Register-tiled: 256 threads compute 64 nodes x 64 cols (4x4 per thread).
// If x != nullptr, the input h is computed on the fly as x @ embW + embB
// (fused embed — the embed output is consumed only here).
__global__ void __launch_bounds__(256) k_gat_lin(
        const float* __restrict__ W,
        const float* __restrict__ asrc,
        const float* __restrict__ adst,
        const float* __restrict__ x,      // nullable
        const float* __restrict__ embW,
        const float* __restrict__ embB) {
    __shared__ float sW[64 * 64];
    __shared__ float sIn[64 * 68];    // transposed [k][node], stride 68
    __shared__ float sA[64], sD[64];
    __shared__ float sX[64 * 5];
    __shared__ float sEW[5 * 64];
    __shared__ float sEB[64];
    int t = threadIdx.x;
    int base = blockIdx.x * 64;       // grid = NN/64 exactly
#pragma unroll 4
    for (int i = t; i < 4096; i += 256) sW[i] = W[i];
    if (t < 64)             sA[t]      = asrc[t];
    else if (t < 128)       sD[t - 64] = adst[t - 64];

    if (x != nullptr) {
        for (int i = t; i < 320; i += 256) { sX[i] = x[base * 5 + i]; sEW[i] = embW[i]; }
        if (t < 64) sEB[t] = embB[t];
        __syncthreads();
#pragma unroll 4
        for (int i = t; i < 4096; i += 256) {
            int node = i >> 6, k = i & 63;
            float acc = sEB[k];
#pragma unroll
            for (int f = 0; f < 5; f++) acc = fmaf(sX[node * 5 + f], sEW[f * 64 + k], acc);
            sIn[k * 68 + node] = acc;
        }
    } else {
#pragma unroll 4
        for (int i = t; i < 4096; i += 256) {
            int node = i >> 6, k = i & 63;
            sIn[k * 68 + node] = g_h0[(base + node) * 64 + k];
        }
    }
    __syncthreads();

    int tx = t & 15, ty = t >> 4;     // tx: col quad, ty: node quad
    float acc[4][4] = {};
#pragma unroll 8
    for (int k = 0; k < 64; k++) {
        float4 wv = *(const float4*)&sW[k * 64 + tx * 4];
        float4 hv = *(const float4*)&sIn[k * 68 + ty * 4];
#pragma unroll
        for (int i = 0; i < 4; i++) {
            float h = (i == 0) ? hv.x : (i == 1) ? hv.y : (i == 2) ? hv.z : hv.w;
            acc[i][0] = fmaf(h, wv.x, acc[i][0]);
            acc[i][1] = fmaf(h, wv.y, acc[i][1]);
            acc[i][2] = fmaf(h, wv.z, acc[i][2]);
            acc[i][3] = fmaf(h, wv.w, acc[i][3]);
        }
    }
    float a0 = sA[tx * 4], a1 = sA[tx * 4 + 1], a2 = sA[tx * 4 + 2], a3 = sA[tx * 4 + 3];
    float d0 = sD[tx * 4], d1 = sD[tx * 4 + 1], d2 = sD[tx * 4 + 2], d3 = sD[tx * 4 + 3];
#pragma unroll
    for (int i = 0; i < 4; i++) {
        int node = base + ty * 4 + i;
        float4 v = make_float4(acc[i][0], acc[i][1], acc[i][2], acc[i][3]);
        *(float4*)&g_hlin[node * 64 + tx * 4] = v;
        float ps = v.x * a0 + v.y * a1 + v.z * a2 + v.w * a3;
        float pd = v.x * d0 + v.y * d1 + v.z * d2 + v.w * d3;
#pragma unroll
        for (int o = 8; o > 0; o >>= 1) {
            ps += __shfl_down_sync(0xffffffffu, ps, o, 16);
            pd += __shfl_down_sync(0xffffffffu, pd, o, 16);
        }
        if (tx == 0) { g_as[node] = ps; g_ad[node] = pd; }
    }
}

// ---------------- fused per-node aggregation (online softmax) ---------------
__global__ void __launch_bounds__(256) k_node_agg(const float* __restrict__ b, int relu) {
    int warp = (blockIdx.x * 256 + threadIdx.x) >> 5;   // grid = NN/8 blocks
    int lane = threadIdx.x & 31;
    if (warp >= NN) return;
    int n     = warp;
    int start = g_rowstart[n];
    int deg   = g_deg[n];
    float adn = g_ad[n];
    const float2* hb = (const float2*)g_hlin;

    float m = -INFINITY, den = 0.f;
    float ax = 0.f, ay = 0.f;
    for (int base = 0; base < deg; base += 32) {
        int cnt = min(32, deg - base);
        int s = 0;
        float e = -INFINITY;
        if (lane < cnt) {
            s = __ldg(&g_col[start + base + lane]);
            float v = __ldg(&g_as[s]) + adn;
            e = (v > 0.f) ? v : 0.2f * v;
        }
        float mloc = e;
#pragma unroll
        for (int o = 16; o > 0; o >>= 1)
            mloc = fmaxf(mloc, __shfl_xor_sync(0xffffffffu, mloc, o));
        float newm  = fmaxf(m, mloc);
        float scale = __expf(m - newm);        // 0 on first chunk (m=-inf)
        den *= scale; ax *= scale; ay *= scale;
        float w = (lane < cnt) ? __expf(e - newm) : 0.f;
        float wsum = w;
#pragma unroll
        for (int o = 16; o > 0; o >>= 1)
            wsum += __shfl_xor_sync(0xffffffffu, wsum, o);
        den += wsum;
        m = newm;

        int j = 0;
        for (; j + 4 <= cnt; j += 4) {
            int   s0 = __shfl_sync(0xffffffffu, s, j);
            int   s1 = __shfl_sync(0xffffffffu, s, j + 1);
            int   s2 = __shfl_sync(0xffffffffu, s, j + 2);
            int   s3 = __shfl_sync(0xffffffffu, s, j + 3);
            float w0 = __shfl_sync(0xffffffffu, w, j);
            float w1 = __shfl_sync(0xffffffffu, w, j + 1);
            float w2 = __shfl_sync(0xffffffffu, w, j + 2);
            float w3 = __shfl_sync(0xffffffffu, w, j + 3);
            float2 h0 = __ldg(&hb[s0 * 32 + lane]);
            float2 h1 = __ldg(&hb[s1 * 32 + lane]);
            float2 h2 = __ldg(&hb[s2 * 32 + lane]);
            float2 h3 = __ldg(&hb[s3 * 32 + lane]);
            ax = fmaf(w0, h0.x, ax); ay = fmaf(w0, h0.y, ay);
            ax = fmaf(w1, h1.x, ax); ay = fmaf(w1, h1.y, ay);
            ax = fmaf(w2, h2.x, ax); ay = fmaf(w2, h2.y, ay);
            ax = fmaf(w3, h3.x, ax); ay = fmaf(w3, h3.y, ay);
        }
        for (; j < cnt; j++) {
            int   sj = __shfl_sync(0xffffffffu, s, j);
            float wj = __shfl_sync(0xffffffffu, w, j);
            float2 h = __ldg(&hb[sj * 32 + lane]);
            ax = fmaf(wj, h.x, ax); ay = fmaf(wj, h.y, ay);
        }
    }
    float inv = 1.f / (den + 1e-16f);
    float o0 = ax * inv + b[2 * lane];
    float o1 = ay * inv + b[2 * lane + 1];
    if (relu) { o0 = fmaxf(o0, 0.f); o1 = fmaxf(o1, 0.f); }
    ((float2*)g_h0)[n * 32 + lane] = make_float2(o0, o1);
}

// ---------------- pooling: sorted batch, run-length, pipelined reads --------
__global__ void k_pool() {
    int t = threadIdx.x;
    int c = t & 63;
    int n0 = blockIdx.x * 128 + (t >> 6) * 32;   // 4 groups x 32 nodes / block
    if (n0 >= NN) return;
    int nend = min(n0 + 32, NN);

    int   rg   = g_batch[n0];                    // current run's graph
    float v    = g_h0[n0 * 64 + c];
    float lsum = 0.f, lmax = -INFINITY;
    int   lcnt = 0;
    for (int n = n0; n < nend; n++) {
        int   gnext = (n + 1 < nend) ? g_batch[n + 1] : -1;
        float vnext = (n + 1 < nend) ? g_h0[(n + 1) * 64 + c] : 0.f;
        lsum += v; lmax = fmaxf(lmax, v); lcnt++;
        if (gnext != rg) {
            atomicAdd(&g_psum[rg * 64 + c], lsum);
            atomicMax(&g_pmax[rg * 64 + c], fOrd(lmax));
            if (c == 0) atomicAdd(&g_cnt[rg], lcnt);
            rg = gnext; lsum = 0.f; lmax = -INFINITY; lcnt = 0;
        }
        v = vnext;
    }
}

// ---------------- fused head: feat -> fc1 -> fc2 -> fc3 ---------------------
__global__ void __launch_bounds__(256) k_head(
        const float* __restrict__ W1, const float* __restrict__ b1,
        const float* __restrict__ W2, const float* __restrict__ b2,
        const float* __restrict__ W3, const float* __restrict__ b3,
        float* __restrict__ out) {
    __shared__ float sW1[128 * 64];
    __shared__ float sW2[64 * 32];
    __shared__ float sW3[32];
    __shared__ float sFeat[4][128];
    __shared__ float sM1[4][64];
    __shared__ float sM2[4][32];
    int t = threadIdx.x;                        // 4 graphs x 64 cols
    for (int i = t; i < 128 * 64; i += 256) sW1[i] = W1[i];
    for (int i = t; i < 64 * 32;  i += 256) sW2[i] = W2[i];
    if (t < 32) sW3[t] = W3[t];
    int j = t >> 6, c = t & 63;
    int g = blockIdx.x * 4 + j;                 // grid = GG/4
    int n = g_cnt[g];
    sFeat[j][c]      = g_psum[g * 64 + c] / fmaxf((float)n, 1.f);
    sFeat[j][c + 64] = (n > 0) ? fUnord(g_pmax[g * 64 + c]) : 0.f;
    __syncthreads();
    float acc = b1[c];
#pragma unroll 8
    for (int k = 0; k < 128; k++) acc = fmaf(sFeat[j][k], sW1[k * 64 + c], acc);
    sM1[j][c] = fmaxf(acc, 0.f);
    __syncthreads();
    if (c < 32) {
        float a2 = b2[c];
#pragma unroll 8
        for (int k = 0; k < 64; k++) a2 = fmaf(sM1[j][k], sW2[k * 32 + c], a2);
        sM2[j][c] = fmaxf(a2, 0.f);
    }
    __syncthreads();
    if (c == 0) {
        float a3 = b3[0];
#pragma unroll
        for (int k = 0; k < 32; k++) a3 = fmaf(sM2[j][k], sW3[k], a3);
        out[g] = a3;
    }
}

// ---------------- launch ------------------------------------------------------
extern "C" void kernel_launch(void* const* d_in, const int* in_sizes, int n_in,
                              void* d_out, int out_size) {
    const float* x     = (const float*)d_in[0];
    const int*   ei    = (const int*)d_in[1];
    const int*   batch = (const int*)d_in[2];
    const float* embW  = (const float*)d_in[3];
    const float* embB  = (const float*)d_in[4];
    const float* g1W   = (const float*)d_in[5];
    const float* g1as  = (const float*)d_in[6];
    const float* g1ad  = (const float*)d_in[7];
    const float* g1b   = (const float*)d_in[8];
    const float* g2W   = (const float*)d_in[9];
    const float* g2as  = (const float*)d_in[10];
    const float* g2ad  = (const float*)d_in[11];
    const float* g2b   = (const float*)d_in[12];
    const float* fc1W  = (const float*)d_in[13];
    const float* fc1b  = (const float*)d_in[14];
    const float* fc2W  = (const float*)d_in[15];
    const float* fc2b  = (const float*)d_in[16];
    const float* fc3W  = (const float*)d_in[17];
    const float* fc3b  = (const float*)d_in[18];
    float* out = (float*)d_out;

    const int ET_BLOCKS = (ETOT + 255) / 256;       // 5469
    const int N_BLOCKS  = (NN + 255) / 256;         // 782

    k_zero_detect<<<N_BLOCKS, 256>>>(ei);
    k_convert<<<ET_BLOCKS, 256>>>(ei, batch);
    k_alloc<<<(NN + 1023) / 1024, 1024>>>();
    // 4th launch — ncu lands here: the layer-1 GEMM (embed fused).
    k_gat_lin<<<NN / 64, 256>>>(g1W, g1as, g1ad, x, embW, embB);
    k_fill<<<ET_BLOCKS, 256>>>();
    k_node_agg<<<NN / 8, 256>>>(g1b, 1);

    k_gat_lin<<<NN / 64, 256>>>(g2W, g2as, g2ad, nullptr, embW, embB);
    k_node_agg<<<NN / 8, 256>>>(g2b, 0);

    k_pool<<<(NN + 127) / 128, 256>>>();
    k_head<<<GG / 4, 256>>>(fc1W, fc1b, fc2W, fc2b, fc3W, fc3b, out);
}